// round 10
// baseline (speedup 1.0000x reference)
#include <cuda_runtime.h>
#include <math.h>

#define BB 16
#define NN 16384
#define TOTAL (BB * NN)
#define NCHUNK (NN / 32)        // 512

// Scratch (padded so tail prefetches stay in-bounds; pad values never used).
__device__ float4 g_cA[TOTAL + 512];
__device__ float4 g_cB[TOTAL + 512];
__device__ int    g_lo[TOTAL + 512];

// ---------------------------------------------------------------------------
// Pass 1: fully parallel coefficient computation.
//   blk[0]=b0*w0; blk[j]=b0*w[j]+a1*w[j-1] (j=1..5); blk[6]=a1*w5;  B.w=x[n].
//   Stores lo = (n - zc - 6) & 255 (ring slot of the 7-tap window start).
// ---------------------------------------------------------------------------
__global__ void __launch_bounds__(256)
coef_kernel(const float* __restrict__ f0,
            const float* __restrict__ x,
            const float* __restrict__ lb)
{
    int i = blockIdx.x * blockDim.x + threadIdx.x;
    if (i >= TOTAL) return;
    int n = i & (NN - 1);

    float2 gp = reinterpret_cast<const float2*>(lb)[i];
    float g  = 0.99f * gp.x;
    float p  = gp.y;
    float b0 = g * (1.0f - p);
    float a1 = g * p;
    float f0c = f0[i] - a1 / (b0 + a1 + 1e-7f);

    int   zc    = (int)floorf(f0c) - 2;     // in [37, 97]
    float alpha = f0c - (float)zc;          // in [2, 3)

    float u0 = alpha;
    float u1 = alpha - 1.0f;
    float u2 = alpha - 2.0f;
    float u3 = alpha - 3.0f;
    float u4 = alpha - 4.0f;
    float u5 = alpha - 5.0f;

    float pre1 = u0;
    float pre2 = pre1 * u1;
    float pre3 = pre2 * u2;
    float pre4 = pre3 * u3;
    float pre5 = pre4 * u4;
    float suf4 = u5;
    float suf3 = suf4 * u4;
    float suf2 = suf3 * u3;
    float suf1 = suf2 * u2;
    float suf0 = suf1 * u1;

    float w0 = suf0        * (-1.0f / 120.0f);
    float w1 = pre1 * suf1 * ( 1.0f /  24.0f);
    float w2 = pre2 * suf2 * (-1.0f /  12.0f);
    float w3 = pre3 * suf3 * ( 1.0f /  12.0f);
    float w4 = pre4 * suf4 * (-1.0f /  24.0f);
    float w5 = pre5        * ( 1.0f / 120.0f);

    g_cA[i] = make_float4(b0 * w0,
                          fmaf(b0, w1, a1 * w0),
                          fmaf(b0, w2, a1 * w1),
                          fmaf(b0, w3, a1 * w2));
    g_cB[i] = make_float4(fmaf(b0, w4, a1 * w3),
                          fmaf(b0, w5, a1 * w4),
                          a1 * w5,
                          x[i]);
    g_lo[i] = (n - zc - 6) & 255;
}

// ---------------------------------------------------------------------------
// Pass 2: sequential recurrence, ONE warp per batch row, nothing else on the SM.
//   y[n] = x[n] + sum_{j=0..6} blk[j]*y[n-zc-j],  delays in [37, 103].
//   - SMEM ring 256 + 7-slot mirror: branchless 7-tap window, immediate
//     offsets; one __syncwarp per chunk orders STS(c) before LDS(c+1).
//   - pre-zeroed ring + wrap mapping implements the zero initial state.
//   - coefficients: plain LDG into a 4-stage rotating register buffer,
//     issued right after each chunk's sync, consumed 4 chunks (~350 cyc)
//     later -> L2 latency fully covered, no SMEM staging, no helper warp,
//     no __syncthreads, no LSU contention from cp.async.
//   - output STG in-line (fire-and-forget).
// ---------------------------------------------------------------------------
__global__ void __launch_bounds__(32, 1)
lpc_kernel(float* __restrict__ out)
{
    __shared__ float ring[264];

    const int b    = blockIdx.x;
    const int lane = threadIdx.x;
    const bool lane_lt7 = lane < 7;
    const float4* __restrict__ cA = g_cA + b * NN + lane;
    const float4* __restrict__ cB = g_cB + b * NN + lane;
    const int*    __restrict__ cI = g_lo + b * NN + lane;
    float* __restrict__ op = out + b * NN + lane;

    // zero the ring (implements zero initial state via wrap mapping)
#pragma unroll
    for (int k = 0; k < 8; k++) ring[lane + 32 * k] = 0.0f;
    if (lane < 8) ring[256 + lane] = 0.0f;

    // prime 4-stage coefficient buffer with chunks 0..3
    float4 A0 = cA[0 * 32], B0 = cB[0 * 32];
    float4 A1 = cA[1 * 32], B1 = cB[1 * 32];
    float4 A2 = cA[2 * 32], B2 = cB[2 * 32];
    float4 A3 = cA[3 * 32], B3 = cB[3 * 32];
    int l0 = cI[0 * 32];
    int l1 = cI[1 * 32];
    int l2 = cI[2 * 32];
    int l3 = cI[3 * 32];
    cA += 4 * 32; cB += 4 * 32; cI += 4 * 32;

    __syncwarp();                               // ring zeros visible

    for (int c4 = 0; c4 < NCHUNK; c4 += 4) {
        const int wb = (c4 & 4) << 5;           // 0 or 128
        const bool mir = ((c4 & 4) == 0) && lane_lt7;   // chunk c4 has c%8==0

        // ---- chunk c4+0 ----
        {
            const float* w = ring + l0;
            float v6 = w[0], v5 = w[1], v4 = w[2], v3 = w[3];
            float v2 = w[4], v1 = w[5], v0 = w[6];
            float t0 = fmaf(A0.x, v0, B0.w);
            float t1 = fmaf(A0.z, v2, A0.y * v1);
            float t2 = fmaf(B0.x, v4, A0.w * v3);
            float t3 = fmaf(B0.z, v6, B0.y * v5);
            float acc = (t0 + t1) + (t2 + t3);
            ring[wb + lane] = acc;
            if (mir) ring[256 + lane] = acc;
            op[0 * 32] = acc;
        }
        __syncwarp();
        A0 = cA[0 * 32]; B0 = cB[0 * 32]; l0 = cI[0 * 32];   // chunk c4+4

        // ---- chunk c4+1 ----
        {
            const float* w = ring + l1;
            float v6 = w[0], v5 = w[1], v4 = w[2], v3 = w[3];
            float v2 = w[4], v1 = w[5], v0 = w[6];
            float t0 = fmaf(A1.x, v0, B1.w);
            float t1 = fmaf(A1.z, v2, A1.y * v1);
            float t2 = fmaf(B1.x, v4, A1.w * v3);
            float t3 = fmaf(B1.z, v6, B1.y * v5);
            float acc = (t0 + t1) + (t2 + t3);
            ring[wb + 32 + lane] = acc;
            op[1 * 32] = acc;
        }
        __syncwarp();
        A1 = cA[1 * 32]; B1 = cB[1 * 32]; l1 = cI[1 * 32];   // chunk c4+5

        // ---- chunk c4+2 ----
        {
            const float* w = ring + l2;
            float v6 = w[0], v5 = w[1], v4 = w[2], v3 = w[3];
            float v2 = w[4], v1 = w[5], v0 = w[6];
            float t0 = fmaf(A2.x, v0, B2.w);
            float t1 = fmaf(A2.z, v2, A2.y * v1);
            float t2 = fmaf(B2.x, v4, A2.w * v3);
            float t3 = fmaf(B2.z, v6, B2.y * v5);
            float acc = (t0 + t1) + (t2 + t3);
            ring[wb + 64 + lane] = acc;
            op[2 * 32] = acc;
        }
        __syncwarp();
        A2 = cA[2 * 32]; B2 = cB[2 * 32]; l2 = cI[2 * 32];   // chunk c4+6

        // ---- chunk c4+3 ----
        {
            const float* w = ring + l3;
            float v6 = w[0], v5 = w[1], v4 = w[2], v3 = w[3];
            float v2 = w[4], v1 = w[5], v0 = w[6];
            float t0 = fmaf(A3.x, v0, B3.w);
            float t1 = fmaf(A3.z, v2, A3.y * v1);
            float t2 = fmaf(B3.x, v4, A3.w * v3);
            float t3 = fmaf(B3.z, v6, B3.y * v5);
            float acc = (t0 + t1) + (t2 + t3);
            ring[wb + 96 + lane] = acc;
            op[3 * 32] = acc;
        }
        __syncwarp();
        A3 = cA[3 * 32]; B3 = cB[3 * 32]; l3 = cI[3 * 32];   // chunk c4+7

        cA += 128; cB += 128; cI += 128; op += 128;
    }
}

// ---------------------------------------------------------------------------
// Inputs (metadata order): f0 [B,N] f32, x [B,N] f32, l_b [B,N,2] f32, K int32
// Output: y [B,N] f32
// ---------------------------------------------------------------------------
extern "C" void kernel_launch(void* const* d_in, const int* in_sizes, int n_in,
                              void* d_out, int out_size)
{
    const float* f0 = (const float*)d_in[0];
    const float* x  = (const float*)d_in[1];
    const float* lb = (const float*)d_in[2];
    float* out = (float*)d_out;

    coef_kernel<<<TOTAL / 256, 256>>>(f0, x, lb);
    lpc_kernel<<<BB, 32>>>(out);
}

// round 11
// speedup vs baseline: 1.7257x; 1.7257x over previous
#include <cuda_runtime.h>
#include <math.h>

#define BB 16
#define NN 16384
#define TOTAL (BB * NN)
#define NCHUNK (NN / 32)        // 512
#define NGROUP (NCHUNK / 4)     // 128 groups of 4 chunks

// Scratch (padded so tail prefetches stay in-bounds; pad values never used).
__device__ float4 g_cA[TOTAL + 512];
__device__ float4 g_cB[TOTAL + 512];
__device__ int    g_lo[TOTAL + 512];

// ---------------------------------------------------------------------------
// Pass 1: fully parallel coefficient computation.
//   blk[0]=b0*w0; blk[j]=b0*w[j]+a1*w[j-1] (j=1..5); blk[6]=a1*w5;  B.w=x[n].
//   Stores lo = (n - zc - 6) & 255 (ring slot of the 7-tap window start).
// ---------------------------------------------------------------------------
__global__ void __launch_bounds__(256)
coef_kernel(const float* __restrict__ f0,
            const float* __restrict__ x,
            const float* __restrict__ lb)
{
    int i = blockIdx.x * blockDim.x + threadIdx.x;
    if (i >= TOTAL) return;
    int n = i & (NN - 1);

    float2 gp = reinterpret_cast<const float2*>(lb)[i];
    float g  = 0.99f * gp.x;
    float p  = gp.y;
    float b0 = g * (1.0f - p);
    float a1 = g * p;
    float f0c = f0[i] - a1 / (b0 + a1 + 1e-7f);

    int   zc    = (int)floorf(f0c) - 2;     // in [37, 97]
    float alpha = f0c - (float)zc;          // in [2, 3)

    float u0 = alpha;
    float u1 = alpha - 1.0f;
    float u2 = alpha - 2.0f;
    float u3 = alpha - 3.0f;
    float u4 = alpha - 4.0f;
    float u5 = alpha - 5.0f;

    float pre1 = u0;
    float pre2 = pre1 * u1;
    float pre3 = pre2 * u2;
    float pre4 = pre3 * u3;
    float pre5 = pre4 * u4;
    float suf4 = u5;
    float suf3 = suf4 * u4;
    float suf2 = suf3 * u3;
    float suf1 = suf2 * u2;
    float suf0 = suf1 * u1;

    float w0 = suf0        * (-1.0f / 120.0f);
    float w1 = pre1 * suf1 * ( 1.0f /  24.0f);
    float w2 = pre2 * suf2 * (-1.0f /  12.0f);
    float w3 = pre3 * suf3 * ( 1.0f /  12.0f);
    float w4 = pre4 * suf4 * (-1.0f /  24.0f);
    float w5 = pre5        * ( 1.0f / 120.0f);

    g_cA[i] = make_float4(b0 * w0,
                          fmaf(b0, w1, a1 * w0),
                          fmaf(b0, w2, a1 * w1),
                          fmaf(b0, w3, a1 * w2));
    g_cB[i] = make_float4(fmaf(b0, w4, a1 * w3),
                          fmaf(b0, w5, a1 * w4),
                          a1 * w5,
                          x[i]);
    g_lo[i] = (n - zc - 6) & 255;
}

// ---------------------------------------------------------------------------
// cp.async helpers
// ---------------------------------------------------------------------------
__device__ __forceinline__ void cp16(void* dst, const void* src) {
    unsigned int d = (unsigned int)__cvta_generic_to_shared(dst);
    asm volatile("cp.async.ca.shared.global [%0], [%1], 16;" :: "r"(d), "l"(src));
}
__device__ __forceinline__ void cp4(void* dst, const void* src) {
    unsigned int d = (unsigned int)__cvta_generic_to_shared(dst);
    asm volatile("cp.async.ca.shared.global [%0], [%1], 4;" :: "r"(d), "l"(src));
}
__device__ __forceinline__ void cp_commit() {
    asm volatile("cp.async.commit_group;");
}
__device__ __forceinline__ void cp_wait1() {
    asm volatile("cp.async.wait_group 1;");
}
// Rendezvous between the two compute warps only (64 threads). BAR.SYNC has
// HW-native memory-fence semantics: the owner's ring STS drain before release.
__device__ __forceinline__ void bar1() {
    asm volatile("bar.sync 1, 64;" ::: "memory");
}

// ---------------------------------------------------------------------------
// Pass 2: sequential recurrence. One block = 3 warps per batch row.
//   warps 0,1 (compute, ping-pong): warp0 owns even chunks, warp1 odd.
//     bar.sync 1,64 between consecutive chunks hands off; between its turns
//     each warp does ALL housekeeping (next-group coefficient LDS from the
//     SMEM stage) in the other warp's shadow, so the critical path between
//     barriers is exactly: 7 ring LDS + 8 FMA + ring STS.
//   warp 2 (helper): cp.async coefficient stream (16-stage, wait_group 1 =>
//     group g+2 resident during group g) + output copy ring->gmem of group
//     g-1; one __syncthreads per 4-chunk group.
//   Ring: 256 + 7-slot mirror, pre-zeroed => zero initial state free; window
//   [lo, lo+6] never wraps (mirror), immediate-offset branchless LDS.
// ---------------------------------------------------------------------------
struct SmemCoef {
    float4 A[16][32];
    float4 B[16][32];
    int    I[16][32];
};

__device__ __forceinline__ void prefetch_chunk(SmemCoef* s, int st, int c, int lane,
                                               const float4* cA, const float4* cB,
                                               const int* cI)
{
    int idx = c * 32 + lane;
    cp16(&s->A[st][lane], cA + idx);
    cp16(&s->B[st][lane], cB + idx);
    cp4 (&s->I[st][lane], cI + idx);
}

__device__ __forceinline__ void do_chunk(float4 A, float4 B, int lo,
                                         float* ring, int wslot, int lane, bool mir)
{
    const float* w = ring + lo;              // window [lo, lo+6], never wraps
    float v6 = w[0], v5 = w[1], v4 = w[2], v3 = w[3];
    float v2 = w[4], v1 = w[5], v0 = w[6];
    float t0 = fmaf(A.x, v0, B.w);           // x[n] + blk0*v0
    float t1 = fmaf(A.z, v2, A.y * v1);
    float t2 = fmaf(B.x, v4, A.w * v3);
    float t3 = fmaf(B.z, v6, B.y * v5);
    float acc = (t0 + t1) + (t2 + t3);
    ring[wslot + lane] = acc;
    if (mir) ring[256 + lane] = acc;
}

__global__ void __launch_bounds__(96, 1)
lpc_kernel(float* __restrict__ out)
{
    __shared__ SmemCoef sc;
    __shared__ float ring[264];

    const int b    = blockIdx.x;
    const int tid  = threadIdx.x;
    const int wid  = tid >> 5;
    const int lane = tid & 31;
    const float4* __restrict__ cA = g_cA + b * NN;
    const float4* __restrict__ cB = g_cB + b * NN;
    const int*    __restrict__ cI = g_lo + b * NN;

    if (wid == 0) {
        // zero the ring (implements zero initial state via wrap mapping)
#pragma unroll
        for (int k = 0; k < 8; k++) ring[lane + 32 * k] = 0.0f;
        if (lane < 8) ring[256 + lane] = 0.0f;
    } else if (wid == 2) {
        // prime pipeline: groups 0,1,2 -> stages 0-11
#pragma unroll
        for (int gp = 0; gp < 3; gp++) {
#pragma unroll
            for (int k = 0; k < 4; k++)
                prefetch_chunk(&sc, gp * 4 + k, gp * 4 + k, lane, cA, cB, cI);
            cp_commit();
        }
        cp_wait1();                       // groups 0 and 1 resident
    }
    __syncthreads();

    if (wid < 2) {
        // ---------------- compute warps (ping-pong) ----------------
        const int  w = wid;                       // owns chunks 4g+w, 4g+w+2
        const bool lane_lt7 = lane < 7;

        // group 0 coefficients for this warp's two chunks
        float4 A0 = sc.A[w    ][lane], B0 = sc.B[w    ][lane];
        float4 A1 = sc.A[w + 2][lane], B1 = sc.B[w + 2][lane];
        int    l0 = sc.I[w    ][lane];
        int    l1 = sc.I[w + 2][lane];

        for (int g = 0; g < NGROUP; g++) {
            const int wb = (g & 1) * 128;          // ring write base
            const int sn = ((g + 1) & 3) * 4;      // next group's stage base
            float4 nA0, nB0, nA1, nB1;
            int    nl0, nl1;

            // chunk 4g+0 (w0) | w1 shadow: load next-group first coef
            if (w == 0) {
                do_chunk(A0, B0, l0, ring, wb, lane, ((g & 1) == 0) && lane_lt7);
            } else {
                nA0 = sc.A[sn + 1][lane]; nB0 = sc.B[sn + 1][lane];
                nl0 = sc.I[sn + 1][lane];
            }
            bar1();
            // chunk 4g+1 (w1) | w0 shadow
            if (w == 1) {
                do_chunk(A0, B0, l0, ring, wb + 32, lane, false);
            } else {
                nA0 = sc.A[sn + 0][lane]; nB0 = sc.B[sn + 0][lane];
                nl0 = sc.I[sn + 0][lane];
            }
            bar1();
            // chunk 4g+2 (w0) | w1 shadow
            if (w == 0) {
                do_chunk(A1, B1, l1, ring, wb + 64, lane, false);
            } else {
                nA1 = sc.A[sn + 3][lane]; nB1 = sc.B[sn + 3][lane];
                nl1 = sc.I[sn + 3][lane];
            }
            bar1();
            // chunk 4g+3 (w1) | w0 shadow
            if (w == 1) {
                do_chunk(A1, B1, l1, ring, wb + 96, lane, false);
            } else {
                nA1 = sc.A[sn + 2][lane]; nB1 = sc.B[sn + 2][lane];
                nl1 = sc.I[sn + 2][lane];
            }

            A0 = nA0; B0 = nB0; l0 = nl0;
            A1 = nA1; B1 = nB1; l1 = nl1;

            __syncthreads();                       // group boundary (all warps)
        }
    } else {
        // ---------------- helper warp ----------------
        float* __restrict__ op = out + b * NN;

        for (int g = 0; g < NGROUP; g++) {
            const int pg = g + 3;                  // group to prefetch
            const int st = (pg & 3) * 4;
#pragma unroll
            for (int k = 0; k < 4; k++)
                prefetch_chunk(&sc, st + k, pg * 4 + k, lane, cA, cB, cI);
            cp_commit();
            cp_wait1();                            // group g+2 resident

            if (g >= 1) {                          // copy group g-1 -> gmem
                const int rb = ((g - 1) & 1) * 128;
                float* o = op + (g - 1) * 128 + lane;
#pragma unroll
                for (int k = 0; k < 4; k++)
                    o[k * 32] = ring[rb + k * 32 + lane];
            }
            __syncthreads();
        }
        // final group's output (last __syncthreads drained compute's STS)
        {
            const int rb = ((NGROUP - 1) & 1) * 128;
            float* o = op + (NGROUP - 1) * 128 + lane;
#pragma unroll
            for (int k = 0; k < 4; k++)
                o[k * 32] = ring[rb + k * 32 + lane];
        }
    }
}

// ---------------------------------------------------------------------------
// Inputs (metadata order): f0 [B,N] f32, x [B,N] f32, l_b [B,N,2] f32, K int32
// Output: y [B,N] f32
// ---------------------------------------------------------------------------
extern "C" void kernel_launch(void* const* d_in, const int* in_sizes, int n_in,
                              void* d_out, int out_size)
{
    const float* f0 = (const float*)d_in[0];
    const float* x  = (const float*)d_in[1];
    const float* lb = (const float*)d_in[2];
    float* out = (float*)d_out;

    coef_kernel<<<TOTAL / 256, 256>>>(f0, x, lb);
    lpc_kernel<<<BB, 96>>>(out);
}